// round 7
// baseline (speedup 1.0000x reference)
#include <cuda_runtime.h>
#include <cuda_bf16.h>
#include <cstdint>

typedef unsigned long long u64;

#define B_    8
#define CM_   64
#define CQ_   64
#define CIN_  128
#define CO_   64
#define H_    128
#define W_    128
#define K_    9
#define JOFF_ 27
#define HW_   (H_*W_)

// Scratch (no cudaMalloc allowed).
__device__ __align__(16) float  g_off[B_*JOFF_*HW_];      // [b][j][h][w]
__device__ __align__(16) float2 g_woff2[CIN_*9*32];       // [c][tap][slot32] dup {w,w}
// Deform weights bf16 hi/lo, layout [tap][hi|lo][n=o][k=c] row-major (k contiguous)
__device__ __align__(16) __nv_bfloat16 g_wbf[K_*2*4096];

__device__ __forceinline__ u64 pack2(float lo, float hi) {
    u64 r; asm("mov.b64 %0, {%1,%2};" : "=l"(r) : "f"(lo), "f"(hi)); return r;
}
__device__ __forceinline__ void ffma2(u64 &d, u64 a, u64 b) {
    asm("fma.rn.f32x2 %0, %1, %2, %0;" : "+l"(d) : "l"(a), "l"(b));
}
union W4 { float4 f; u64 d[2]; };

__device__ __forceinline__ uint32_t smem_u32(const void* p) {
    uint32_t a;
    asm("{ .reg .u64 t; cvta.to.shared.u64 t, %1; cvt.u32.u64 %0, t; }" : "=r"(a) : "l"(p));
    return a;
}

// ---------------------------------------------------------------------------
// Prep: offset-conv weights (dup f32x2) + deform weights (bf16 hi/lo, [n][k]).
// ---------------------------------------------------------------------------
#define N_WOFF (CIN_*9*32)      // 36864
#define N_WB   (K_*64*64)       // 36864
__global__ void prep_weights_kernel(const float* __restrict__ w_off,
                                    const float* __restrict__ w_def) {
    int i = blockIdx.x * 256 + threadIdx.x;
    if (i < N_WOFF) {
        int c = i / 288;
        int r = i - c*288;
        int tap = r / 32;
        int s = r & 31;
        int jg = s >> 3, jj = s & 7;
        int j = jg*7 + jj;
        float v = (jj < 7 && j < JOFF_) ? w_off[(j*CIN_ + c)*9 + tap] : 0.f;
        g_woff2[i] = make_float2(v, v);
    } else if (i < N_WOFF + N_WB) {
        int i2 = i - N_WOFF;
        int tap = i2 / 4096;
        int r = i2 - tap*4096;
        int n = r >> 6;          // output channel o
        int c = r & 63;          // input channel (k)
        float w = w_def[(n*CM_ + c)*K_ + tap];
        __nv_bfloat16 hi = __float2bfloat16_rn(w);
        __nv_bfloat16 lo = __float2bfloat16_rn(w - __bfloat162float(hi));
        g_wbf[tap*8192 + n*64 + c]        = hi;
        g_wbf[tap*8192 + 4096 + n*64 + c] = lo;
    }
}

// ---------------------------------------------------------------------------
// Offset conv (unchanged from R5): SIMT FFMA2, reg-staged pipeline.
// ---------------------------------------------------------------------------
__global__ __launch_bounds__(128) void offset_conv_kernel(
        const float* __restrict__ mem, const float* __restrict__ que,
        const float* __restrict__ b_off) {
    __shared__ float2 sx[2][4][130];
    __shared__ __align__(16) float2 sw[2][9][32];

    const int bid = blockIdx.x;
    const int b   = bid >> 6;
    const int h0  = (bid & 63) * 2;
    const int tid = threadIdx.x;
    const int r2  = tid >> 6;
    const int t   = tid & 63;
    const int ps  = t & 15;
    const int jg  = t >> 4;

    u64 acc[4][7];
    #pragma unroll
    for (int jj = 0; jj < 7; jj++) {
        int j = jg*7 + jj;
        float bias = (j < JOFF_) ? b_off[j] : 0.f;
        #pragma unroll
        for (int i = 0; i < 4; i++) acc[i][jj] = pack2(bias, bias);
    }

    float2 xreg[5];
    float2 wreg[3];

    #define LOAD_REGS(c) do {                                                 \
        const float* xc = ((c) < CM_) ? (mem + (size_t)(b*CM_ + (c))*HW_)     \
                                      : (que + (size_t)(b*CQ_ + ((c)-CM_))*HW_);\
        _Pragma("unroll")                                                     \
        for (int s = 0; s < 5; s++) {                                         \
            int e = tid + 128*s;                                              \
            float lo = 0.f, hi = 0.f;                                         \
            if (e < 520) {                                                    \
                int r = e / 130, i = e - r*130;                               \
                int row = h0 + r - 1;                                         \
                if (row >= 0 && row < H_) {                                   \
                    const float* xr = xc + row*W_;                            \
                    if (i >= 1 && i <= 128) lo = xr[i-1];                     \
                    if (i <= 127)           hi = xr[i];                       \
                }                                                             \
            }                                                                 \
            xreg[s] = make_float2(lo, hi);                                    \
        }                                                                     \
        const float2* wsrc = g_woff2 + (size_t)(c)*288;                       \
        _Pragma("unroll")                                                     \
        for (int s = 0; s < 3; s++) {                                         \
            int e = tid + 128*s;                                              \
            wreg[s] = (e < 288) ? wsrc[e] : make_float2(0.f, 0.f);            \
        }                                                                     \
    } while (0)

    #define STORE_REGS(p) do {                                                \
        _Pragma("unroll")                                                     \
        for (int s = 0; s < 5; s++) {                                         \
            int e = tid + 128*s;                                              \
            if (e < 520) { int r = e / 130, i = e - r*130; sx[p][r][i] = xreg[s]; } \
        }                                                                     \
        _Pragma("unroll")                                                     \
        for (int s = 0; s < 3; s++) {                                         \
            int e = tid + 128*s;                                              \
            if (e < 288) { int tp = e >> 5; sw[p][tp][e & 31] = wreg[s]; }    \
        }                                                                     \
    } while (0)

    LOAD_REGS(0);
    STORE_REGS(0);
    __syncthreads();

    for (int c = 0; c < CIN_; c++) {
        const int p = c & 1;
        if (c + 1 < CIN_) LOAD_REGS(c + 1);
        #pragma unroll
        for (int tap = 0; tap < 9; tap++) {
            const int ky = tap / 3, kx = tap - ky*3;
            u64 xv[4];
            #pragma unroll
            for (int i = 0; i < 4; i++)
                xv[i] = *(const u64*)&sx[p][r2 + ky][2*(ps + 16*i) + kx];
            W4 wq[4];
            #pragma unroll
            for (int m = 0; m < 4; m++)
                wq[m].f = *(const float4*)&sw[p][tap][jg*8 + 2*m];
            #pragma unroll
            for (int i = 0; i < 4; i++)
                #pragma unroll
                for (int m = 0; m < 4; m++) {
                    ffma2(acc[i][2*m], xv[i], wq[m].d[0]);
                    if (m < 3) ffma2(acc[i][2*m+1], xv[i], wq[m].d[1]);
                }
        }
        if (c + 1 < CIN_) STORE_REGS(p ^ 1);
        __syncthreads();
    }
    #undef LOAD_REGS
    #undef STORE_REGS

    const int h = h0 + r2;
    #pragma unroll
    for (int jj = 0; jj < 7; jj++) {
        int j = jg*7 + jj;
        if (j < JOFF_) {
            #pragma unroll
            for (int i = 0; i < 4; i++) {
                u64* dst = (u64*)(g_off + ((size_t)(b*JOFF_ + j)*H_ + h)*W_ + 2*(ps + 16*i));
                *dst = acc[i][jj];
            }
        }
    }
}

// ---------------------------------------------------------------------------
// Deformable conv on warp-level mma.sync (bf16 hi/lo split, fp32 accum).
// Block = one (b,h) row, 256 threads / 8 warps; warp w owns pixels 16w..16w+15.
// Per tap: sample A (warp-local rows) + stage B[tap] (block), then
// 4 k-steps x 8 n-tiles x 3 split-term MMAs per warp.
// Smem: Ahi/Alo 128x64 bf16 + Bhi/Blo 64x64 bf16, XOR-swizzled 128B rows = 48KB.
// ---------------------------------------------------------------------------
#define SWB(row, colb) ((row)*128 + ((((colb) >> 4) ^ ((row) & 7)) << 4) + ((colb) & 15))

__device__ __forceinline__ void ldsm_x4(uint32_t a[4], uint32_t addr) {
    asm volatile("ldmatrix.sync.aligned.m8n8.x4.shared.b16 {%0,%1,%2,%3}, [%4];"
        : "=r"(a[0]), "=r"(a[1]), "=r"(a[2]), "=r"(a[3]) : "r"(addr));
}
__device__ __forceinline__ void ldsm_x2(uint32_t b[2], uint32_t addr) {
    asm volatile("ldmatrix.sync.aligned.m8n8.x2.shared.b16 {%0,%1}, [%2];"
        : "=r"(b[0]), "=r"(b[1]) : "r"(addr));
}
__device__ __forceinline__ void mma16816(float c[4], const uint32_t a[4], const uint32_t b[2]) {
    asm volatile("mma.sync.aligned.m16n8k16.row.col.f32.bf16.bf16.f32 "
        "{%0,%1,%2,%3}, {%4,%5,%6,%7}, {%8,%9}, {%0,%1,%2,%3};"
        : "+f"(c[0]), "+f"(c[1]), "+f"(c[2]), "+f"(c[3])
        : "r"(a[0]), "r"(a[1]), "r"(a[2]), "r"(a[3]), "r"(b[0]), "r"(b[1]));
}

__global__ __launch_bounds__(256) void deform_mma_kernel(
        const float* __restrict__ mem, float* __restrict__ out) {
    __shared__ __align__(16) char smem[49152];   // Ahi 16K | Alo 16K | Bhi 8K | Blo 8K
    char* Ahi = smem;
    char* Alo = smem + 16384;
    char* Bhi = smem + 32768;
    char* Blo = smem + 40960;
    const uint32_t ahi_u = smem_u32(Ahi), alo_u = smem_u32(Alo);
    const uint32_t bhi_u = smem_u32(Bhi), blo_u = smem_u32(Blo);

    const int tid  = threadIdx.x;
    const int lane = tid & 31;
    const int wrp  = tid >> 5;
    const int bh   = blockIdx.x;
    const int b    = bh >> 7;
    const int h    = bh & 127;

    const int px   = tid >> 1;       // pixel this thread samples
    const int half = tid & 1;        // channel half (32 ch each)
    const float* memb = mem + (size_t)b*CM_*HW_ + (size_t)(half*32)*HW_;
    const float* offp = g_off + (size_t)b*JOFF_*HW_ + h*W_ + px;

    float C[8][4];
    #pragma unroll
    for (int nt = 0; nt < 8; nt++)
        #pragma unroll
        for (int i = 0; i < 4; i++) C[nt][i] = 0.f;

    for (int tap = 0; tap < K_; tap++) {
        __syncthreads();   // previous tap's MMAs done; smem reusable

        // ---- stage B[tap] (hi 8KB + lo 8KB), swizzled 16B chunks ----
        {
            const uint4* src = (const uint4*)(g_wbf + (size_t)tap*8192);
            #pragma unroll
            for (int m = 0; m < 4; m++) {
                int e = tid + 256*m;               // 0..1023 uint4 chunks
                uint4 v = src[e];
                int e2 = e & 511;
                int n = e2 >> 3, kc = e2 & 7;      // row n, 16B chunk kc
                char* dst = (e < 512) ? Bhi : Blo;
                *(uint4*)(dst + n*128 + ((kc ^ (n & 7)) << 4)) = v;
            }
        }

        // ---- sample A: bilinear for (px, tap), 32 channels, bf16 hi/lo ----
        {
            float dy  = offp[(2*tap)*HW_];
            float dx  = offp[(2*tap+1)*HW_];
            float msk = offp[(18+tap)*HW_];
            float py  = (float)(h + (tap/3) - 1) + dy;
            float pxx = (float)(px + (tap - (tap/3)*3) - 1) + dx;
            float y0f = floorf(py), x0f = floorf(pxx);
            float fy = py - y0f, fx = pxx - x0f;
            int y0 = (int)y0f, x0 = (int)x0f;
            int y1 = y0 + 1,   x1 = x0 + 1;
            float vy0 = (y0 >= 0 && y0 < H_) ? 1.f : 0.f;
            float vy1 = (y1 >= 0 && y1 < H_) ? 1.f : 0.f;
            float vx0 = (x0 >= 0 && x0 < W_) ? 1.f : 0.f;
            float vx1 = (x1 >= 0 && x1 < W_) ? 1.f : 0.f;
            int y0c = min(max(y0, 0), H_-1), y1c = min(max(y1, 0), H_-1);
            int x0c = min(max(x0, 0), W_-1), x1c = min(max(x1, 0), W_-1);
            float w00 = (1.f-fy)*(1.f-fx)*msk*vy0*vx0;
            float w01 = (1.f-fy)*fx      *msk*vy0*vx1;
            float w10 = fy      *(1.f-fx)*msk*vy1*vx0;
            float w11 = fy      *fx      *msk*vy1*vx1;
            const float* p00 = memb + y0c*W_ + x0c;
            const float* p01 = memb + y0c*W_ + x1c;
            const float* p10 = memb + y1c*W_ + x0c;
            const float* p11 = memb + y1c*W_ + x1c;

            #pragma unroll
            for (int ci = 0; ci < 16; ci++) {
                const int cA = 2*ci;
                float s0 = w00*p00[cA*HW_]     + w01*p01[cA*HW_]
                         + w10*p10[cA*HW_]     + w11*p11[cA*HW_];
                float s1 = w00*p00[(cA+1)*HW_] + w01*p01[(cA+1)*HW_]
                         + w10*p10[(cA+1)*HW_] + w11*p11[(cA+1)*HW_];
                __nv_bfloat16 h0 = __float2bfloat16_rn(s0);
                __nv_bfloat16 h1 = __float2bfloat16_rn(s1);
                __nv_bfloat16 l0 = __float2bfloat16_rn(s0 - __bfloat162float(h0));
                __nv_bfloat16 l1 = __float2bfloat16_rn(s1 - __bfloat162float(h1));
                uint32_t hp = ((uint32_t)__bfloat16_as_ushort(h1) << 16) | __bfloat16_as_ushort(h0);
                uint32_t lp = ((uint32_t)__bfloat16_as_ushort(l1) << 16) | __bfloat16_as_ushort(l0);
                const int c = half*32 + cA;               // global channel
                const int colb = c*2;                      // byte col in 128B row
                uint32_t off = SWB(px, colb);
                *(uint32_t*)(Ahi + off) = hp;
                *(uint32_t*)(Alo + off) = lp;
            }
        }
        __syncwarp();
        __syncthreads();   // B (and everyone's A) ready

        // ---- MMA: 4 k-steps x 8 n-tiles x 3 split terms ----
        const int arow = wrp*16 + (lane & 15);
        const int acolh = ((lane >> 4) & 1) * 16;          // byte offset of k-half
        const int brow_base = lane & 7;
        const int bcolh = ((lane >> 3) & 1) * 16;
        #pragma unroll
        for (int ks = 0; ks < 4; ks++) {
            uint32_t Afh[4], Afl[4];
            uint32_t aoff = SWB(arow, ks*32 + acolh);
            ldsm_x4(Afh, ahi_u + aoff);
            ldsm_x4(Afl, alo_u + aoff);
            #pragma unroll
            for (int nt = 0; nt < 8; nt++) {
                const int brow = nt*8 + brow_base;
                uint32_t boff = SWB(brow, ks*32 + bcolh);
                uint32_t Bfh[2], Bfl[2];
                ldsm_x2(Bfh, bhi_u + boff);
                ldsm_x2(Bfl, blo_u + boff);
                mma16816(C[nt], Afh, Bfh);
                mma16816(C[nt], Afl, Bfh);
                mma16816(C[nt], Afh, Bfl);
            }
        }
    }

    // ---- epilogue: C fragment -> out[b][o][h][w] ----
    {
        const int g = lane >> 2, t = lane & 3;
        const int m0 = wrp*16 + g;
        float* ob = out + (size_t)b*CO_*HW_ + h*W_;
        #pragma unroll
        for (int nt = 0; nt < 8; nt++) {
            const int n0 = nt*8 + 2*t;
            ob[(size_t)n0*HW_ + m0]         = C[nt][0];
            ob[(size_t)(n0+1)*HW_ + m0]     = C[nt][1];
            ob[(size_t)n0*HW_ + m0 + 8]     = C[nt][2];
            ob[(size_t)(n0+1)*HW_ + m0 + 8] = C[nt][3];
        }
    }
}

extern "C" void kernel_launch(void* const* d_in, const int* in_sizes, int n_in,
                              void* d_out, int out_size) {
    const float* mem   = (const float*)d_in[0];
    const float* que   = (const float*)d_in[1];
    const float* w_off = (const float*)d_in[2];
    const float* b_off = (const float*)d_in[3];
    const float* w_def = (const float*)d_in[4];
    float* out = (float*)d_out;

    prep_weights_kernel<<<(N_WOFF + N_WB + 255)/256, 256>>>(w_off, w_def);
    offset_conv_kernel<<<B_*H_/2, 128>>>(mem, que, b_off);
    deform_mma_kernel<<<B_*H_, 256>>>(mem, out);
}

// round 9
// speedup vs baseline: 1.2027x; 1.2027x over previous
#include <cuda_runtime.h>
#include <cuda_bf16.h>
#include <cstdint>

typedef unsigned long long u64;

#define B_    8
#define CM_   64
#define CQ_   64
#define CIN_  128
#define CO_   64
#define H_    128
#define W_    128
#define K_    9
#define JOFF_ 27
#define HW_   (H_*W_)

// Scratch (no cudaMalloc allowed).
__device__ __align__(16) float  g_off[B_*JOFF_*HW_];      // [b][j][h][w]
__device__ __align__(16) float2 g_woff2[CIN_*9*32];       // [c][tap][slot32] dup {w,w}
__device__ __align__(16) __nv_bfloat16 g_wbf[K_*2*4096];  // [tap][hi|lo][n][k]
__device__ __align__(16) float  g_memT[B_*HW_*CM_];       // channel-last mem [b][h][w][c]

__device__ __forceinline__ u64 pack2(float lo, float hi) {
    u64 r; asm("mov.b64 %0, {%1,%2};" : "=l"(r) : "f"(lo), "f"(hi)); return r;
}
__device__ __forceinline__ void ffma2(u64 &d, u64 a, u64 b) {
    asm("fma.rn.f32x2 %0, %1, %2, %0;" : "+l"(d) : "l"(a), "l"(b));
}
union W4 { float4 f; u64 d[2]; };

__device__ __forceinline__ uint32_t smem_u32(const void* p) {
    uint32_t a;
    asm("{ .reg .u64 t; cvta.to.shared.u64 t, %1; cvt.u32.u64 %0, t; }" : "=r"(a) : "l"(p));
    return a;
}

// ---------------------------------------------------------------------------
// Prep: offset-conv weights (dup f32x2) + deform weights (bf16 hi/lo, [n][k]).
// ---------------------------------------------------------------------------
#define N_WOFF (CIN_*9*32)      // 36864
#define N_WB   (K_*64*64)       // 36864
__global__ void prep_weights_kernel(const float* __restrict__ w_off,
                                    const float* __restrict__ w_def) {
    int i = blockIdx.x * 256 + threadIdx.x;
    if (i < N_WOFF) {
        int c = i / 288;
        int r = i - c*288;
        int tap = r / 32;
        int s = r & 31;
        int jg = s >> 3, jj = s & 7;
        int j = jg*7 + jj;
        float v = (jj < 7 && j < JOFF_) ? w_off[(j*CIN_ + c)*9 + tap] : 0.f;
        g_woff2[i] = make_float2(v, v);
    } else if (i < N_WOFF + N_WB) {
        int i2 = i - N_WOFF;
        int tap = i2 / 4096;
        int r = i2 - tap*4096;
        int n = r >> 6;
        int c = r & 63;
        float w = w_def[(n*CM_ + c)*K_ + tap];
        __nv_bfloat16 hi = __float2bfloat16_rn(w);
        __nv_bfloat16 lo = __float2bfloat16_rn(w - __bfloat162float(hi));
        g_wbf[tap*8192 + n*64 + c]        = hi;
        g_wbf[tap*8192 + 4096 + n*64 + c] = lo;
    }
}

// ---------------------------------------------------------------------------
// Transpose mem -> channel-last g_memT[b][h][w][c]. Block = one (b,h) row.
// ---------------------------------------------------------------------------
__global__ __launch_bounds__(256) void transpose_mem_kernel(const float* __restrict__ mem) {
    __shared__ float tile[64][129];
    const int bh = blockIdx.x;
    const int b = bh >> 7, h = bh & 127;
    const int tid = threadIdx.x;
    const float* src = mem + (size_t)b*CM_*HW_ + h*W_;
    #pragma unroll
    for (int m = 0; m < 32; m++) {
        int e = tid + 256*m;
        int c = e >> 7, w = e & 127;
        tile[c][w] = src[(size_t)c*HW_ + w];
    }
    __syncthreads();
    float* dst = g_memT + ((size_t)b*HW_ + h*W_)*64;
    #pragma unroll
    for (int m = 0; m < 32; m++) {
        int e = tid + 256*m;
        int w = e >> 6, c = e & 63;
        dst[(size_t)w*64 + c] = tile[c][w];
    }
}

// ---------------------------------------------------------------------------
// Offset conv (unchanged from R5): SIMT FFMA2, reg-staged pipeline.
// ---------------------------------------------------------------------------
__global__ __launch_bounds__(128) void offset_conv_kernel(
        const float* __restrict__ mem, const float* __restrict__ que,
        const float* __restrict__ b_off) {
    __shared__ float2 sx[2][4][130];
    __shared__ __align__(16) float2 sw[2][9][32];

    const int bid = blockIdx.x;
    const int b   = bid >> 6;
    const int h0  = (bid & 63) * 2;
    const int tid = threadIdx.x;
    const int r2  = tid >> 6;
    const int t   = tid & 63;
    const int ps  = t & 15;
    const int jg  = t >> 4;

    u64 acc[4][7];
    #pragma unroll
    for (int jj = 0; jj < 7; jj++) {
        int j = jg*7 + jj;
        float bias = (j < JOFF_) ? b_off[j] : 0.f;
        #pragma unroll
        for (int i = 0; i < 4; i++) acc[i][jj] = pack2(bias, bias);
    }

    float2 xreg[5];
    float2 wreg[3];

    #define LOAD_REGS(c) do {                                                 \
        const float* xc = ((c) < CM_) ? (mem + (size_t)(b*CM_ + (c))*HW_)     \
                                      : (que + (size_t)(b*CQ_ + ((c)-CM_))*HW_);\
        _Pragma("unroll")                                                     \
        for (int s = 0; s < 5; s++) {                                         \
            int e = tid + 128*s;                                              \
            float lo = 0.f, hi = 0.f;                                         \
            if (e < 520) {                                                    \
                int r = e / 130, i = e - r*130;                               \
                int row = h0 + r - 1;                                         \
                if (row >= 0 && row < H_) {                                   \
                    const float* xr = xc + row*W_;                            \
                    if (i >= 1 && i <= 128) lo = xr[i-1];                     \
                    if (i <= 127)           hi = xr[i];                       \
                }                                                             \
            }                                                                 \
            xreg[s] = make_float2(lo, hi);                                    \
        }                                                                     \
        const float2* wsrc = g_woff2 + (size_t)(c)*288;                       \
        _Pragma("unroll")                                                     \
        for (int s = 0; s < 3; s++) {                                         \
            int e = tid + 128*s;                                              \
            wreg[s] = (e < 288) ? wsrc[e] : make_float2(0.f, 0.f);            \
        }                                                                     \
    } while (0)

    #define STORE_REGS(p) do {                                                \
        _Pragma("unroll")                                                     \
        for (int s = 0; s < 5; s++) {                                         \
            int e = tid + 128*s;                                              \
            if (e < 520) { int r = e / 130, i = e - r*130; sx[p][r][i] = xreg[s]; } \
        }                                                                     \
        _Pragma("unroll")                                                     \
        for (int s = 0; s < 3; s++) {                                         \
            int e = tid + 128*s;                                              \
            if (e < 288) { int tp = e >> 5; sw[p][tp][e & 31] = wreg[s]; }    \
        }                                                                     \
    } while (0)

    LOAD_REGS(0);
    STORE_REGS(0);
    __syncthreads();

    for (int c = 0; c < CIN_; c++) {
        const int p = c & 1;
        if (c + 1 < CIN_) LOAD_REGS(c + 1);
        #pragma unroll
        for (int tap = 0; tap < 9; tap++) {
            const int ky = tap / 3, kx = tap - ky*3;
            u64 xv[4];
            #pragma unroll
            for (int i = 0; i < 4; i++)
                xv[i] = *(const u64*)&sx[p][r2 + ky][2*(ps + 16*i) + kx];
            W4 wq[4];
            #pragma unroll
            for (int m = 0; m < 4; m++)
                wq[m].f = *(const float4*)&sw[p][tap][jg*8 + 2*m];
            #pragma unroll
            for (int i = 0; i < 4; i++)
                #pragma unroll
                for (int m = 0; m < 4; m++) {
                    ffma2(acc[i][2*m], xv[i], wq[m].d[0]);
                    if (m < 3) ffma2(acc[i][2*m+1], xv[i], wq[m].d[1]);
                }
        }
        if (c + 1 < CIN_) STORE_REGS(p ^ 1);
        __syncthreads();
    }
    #undef LOAD_REGS
    #undef STORE_REGS

    const int h = h0 + r2;
    #pragma unroll
    for (int jj = 0; jj < 7; jj++) {
        int j = jg*7 + jj;
        if (j < JOFF_) {
            #pragma unroll
            for (int i = 0; i < 4; i++) {
                u64* dst = (u64*)(g_off + ((size_t)(b*JOFF_ + j)*H_ + h)*W_ + 2*(ps + 16*i));
                *dst = acc[i][jj];
            }
        }
    }
}

// ---------------------------------------------------------------------------
// Deformable conv, mma.sync + channel-last gather.
// Block = one (b,h) row, 8 warps; warp w owns A-rows (pixels) 16w..16w+15.
// Per tap: stage B (block) + per-warp bilinear params (lanes 0-15, shfl-
// distributed); gather = 8 iters x 2 px, lane = 16B channel chunk ->
// 4 contiguous LDG.128 per 2 pixels per corner. A is warp-private (syncwarp).
// ---------------------------------------------------------------------------
#define SWB(row, colb) ((row)*128 + ((((colb) >> 4) ^ ((row) & 7)) << 4) + ((colb) & 15))

__device__ __forceinline__ void ldsm_x4(uint32_t a[4], uint32_t addr) {
    asm volatile("ldmatrix.sync.aligned.m8n8.x4.shared.b16 {%0,%1,%2,%3}, [%4];"
        : "=r"(a[0]), "=r"(a[1]), "=r"(a[2]), "=r"(a[3]) : "r"(addr));
}
__device__ __forceinline__ void ldsm_x2(uint32_t b[2], uint32_t addr) {
    asm volatile("ldmatrix.sync.aligned.m8n8.x2.shared.b16 {%0,%1}, [%2];"
        : "=r"(b[0]), "=r"(b[1]) : "r"(addr));
}
__device__ __forceinline__ void mma16816(float c[4], const uint32_t a[4], const uint32_t b[2]) {
    asm volatile("mma.sync.aligned.m16n8k16.row.col.f32.bf16.bf16.f32 "
        "{%0,%1,%2,%3}, {%4,%5,%6,%7}, {%8,%9}, {%0,%1,%2,%3};"
        : "+f"(c[0]), "+f"(c[1]), "+f"(c[2]), "+f"(c[3])
        : "r"(a[0]), "r"(a[1]), "r"(a[2]), "r"(a[3]), "r"(b[0]), "r"(b[1]));
}

__global__ __launch_bounds__(256) void deform_mma_kernel(float* __restrict__ out) {
    __shared__ __align__(16) char smem[49152];   // Ahi 16K | Alo 16K | Bhi 8K | Blo 8K
    char* Ahi = smem;
    char* Alo = smem + 16384;
    char* Bhi = smem + 32768;
    char* Blo = smem + 40960;
    const uint32_t ahi_u = smem_u32(Ahi), alo_u = smem_u32(Alo);
    const uint32_t bhi_u = smem_u32(Bhi), blo_u = smem_u32(Blo);

    const int tid  = threadIdx.x;
    const int lane = tid & 31;
    const int wrp  = tid >> 5;
    const int bh   = blockIdx.x;
    const int b    = bh >> 7;
    const int h    = bh & 127;
    const int wbase = wrp * 16;
    const int chunk = lane & 15;

    const char* memTb = (const char*)(g_memT + (size_t)b*HW_*64);
    const float* offrow = g_off + (size_t)b*JOFF_*HW_ + h*W_;

    float C[8][4];
    #pragma unroll
    for (int nt = 0; nt < 8; nt++)
        #pragma unroll
        for (int i = 0; i < 4; i++) C[nt][i] = 0.f;

    for (int tap = 0; tap < K_; tap++) {
        __syncthreads();   // previous tap's MMAs done; B reusable

        // ---- stage B[tap] (hi 8KB + lo 8KB), swizzled 16B chunks ----
        {
            const uint4* src = (const uint4*)(g_wbf + (size_t)tap*8192);
            #pragma unroll
            for (int m = 0; m < 4; m++) {
                int e = tid + 256*m;
                uint4 v = src[e];
                int e2 = e & 511;
                int n = e2 >> 3, kc = e2 & 7;
                char* dst = (e < 512) ? Bhi : Blo;
                *(uint4*)(dst + n*128 + ((kc ^ (n & 7)) << 4)) = v;
            }
        }

        // ---- per-warp bilinear params: lane l computes for px = wbase + (l&15) ----
        float W00, W01, W10, W11;
        int   B00, B01, B10, B11;
        {
            const int ppx = wbase + (lane & 15);
            const float* op = offrow + ppx;
            float dy  = op[(2*tap)*HW_];
            float dx  = op[(2*tap+1)*HW_];
            float msk = op[(18+tap)*HW_];
            float py  = (float)(h + (tap/3) - 1) + dy;
            float pxx = (float)(ppx + (tap - (tap/3)*3) - 1) + dx;
            float y0f = floorf(py), x0f = floorf(pxx);
            float fy = py - y0f, fx = pxx - x0f;
            int y0 = (int)y0f, x0 = (int)x0f;
            int y1 = y0 + 1,   x1 = x0 + 1;
            float vy0 = (y0 >= 0 && y0 < H_) ? 1.f : 0.f;
            float vy1 = (y1 >= 0 && y1 < H_) ? 1.f : 0.f;
            float vx0 = (x0 >= 0 && x0 < W_) ? 1.f : 0.f;
            float vx1 = (x1 >= 0 && x1 < W_) ? 1.f : 0.f;
            int y0c = min(max(y0, 0), H_-1), y1c = min(max(y1, 0), H_-1);
            int x0c = min(max(x0, 0), W_-1), x1c = min(max(x1, 0), W_-1);
            W00 = (1.f-fy)*(1.f-fx)*msk*vy0*vx0;
            W01 = (1.f-fy)*fx      *msk*vy0*vx1;
            W10 = fy      *(1.f-fx)*msk*vy1*vx0;
            W11 = fy      *fx      *msk*vy1*vx1;
            B00 = (y0c*W_ + x0c) << 8;    // *256 bytes (64 ch x 4B per pixel)
            B01 = (y0c*W_ + x1c) << 8;
            B10 = (y1c*W_ + x0c) << 8;
            B11 = (y1c*W_ + x1c) << 8;
        }

        __syncthreads();   // B staged everywhere

        // ---- gather: 8 iters x 2 pixels; lane = 16B channel chunk ----
        #pragma unroll
        for (int i = 0; i < 8; i++) {
            const int sub = 2*i + (lane >> 4);        // px index within warp
            float w00 = __shfl_sync(0xffffffffu, W00, sub);
            float w01 = __shfl_sync(0xffffffffu, W01, sub);
            float w10 = __shfl_sync(0xffffffffu, W10, sub);
            float w11 = __shfl_sync(0xffffffffu, W11, sub);
            int   b00 = __shfl_sync(0xffffffffu, B00, sub);
            int   b01 = __shfl_sync(0xffffffffu, B01, sub);
            int   b10 = __shfl_sync(0xffffffffu, B10, sub);
            int   b11 = __shfl_sync(0xffffffffu, B11, sub);
            const int cb = chunk * 16;
            float4 c00 = *(const float4*)(memTb + b00 + cb);
            float4 c01 = *(const float4*)(memTb + b01 + cb);
            float4 c10 = *(const float4*)(memTb + b10 + cb);
            float4 c11 = *(const float4*)(memTb + b11 + cb);
            float s0 = w00*c00.x + w01*c01.x + w10*c10.x + w11*c11.x;
            float s1 = w00*c00.y + w01*c01.y + w10*c10.y + w11*c11.y;
            float s2 = w00*c00.z + w01*c01.z + w10*c10.z + w11*c11.z;
            float s3 = w00*c00.w + w01*c01.w + w10*c10.w + w11*c11.w;
            __nv_bfloat16 h0 = __float2bfloat16_rn(s0);
            __nv_bfloat16 h1 = __float2bfloat16_rn(s1);
            __nv_bfloat16 h2 = __float2bfloat16_rn(s2);
            __nv_bfloat16 h3 = __float2bfloat16_rn(s3);
            __nv_bfloat16 l0 = __float2bfloat16_rn(s0 - __bfloat162float(h0));
            __nv_bfloat16 l1 = __float2bfloat16_rn(s1 - __bfloat162float(h1));
            __nv_bfloat16 l2 = __float2bfloat16_rn(s2 - __bfloat162float(h2));
            __nv_bfloat16 l3 = __float2bfloat16_rn(s3 - __bfloat162float(h3));
            uint32_t hi01 = ((uint32_t)__bfloat16_as_ushort(h1) << 16) | __bfloat16_as_ushort(h0);
            uint32_t hi23 = ((uint32_t)__bfloat16_as_ushort(h3) << 16) | __bfloat16_as_ushort(h2);
            uint32_t lo01 = ((uint32_t)__bfloat16_as_ushort(l1) << 16) | __bfloat16_as_ushort(l0);
            uint32_t lo23 = ((uint32_t)__bfloat16_as_ushort(l3) << 16) | __bfloat16_as_ushort(l2);
            u64 hiq = ((u64)hi23 << 32) | hi01;
            u64 loq = ((u64)lo23 << 32) | lo01;
            const int px = wbase + sub;
            const uint32_t off = SWB(px, chunk*8);
            *(u64*)(Ahi + off) = hiq;
            *(u64*)(Alo + off) = loq;
        }
        __syncwarp();   // A tile is warp-private

        // ---- MMA: 4 k-steps x 8 n-tiles x 3 split terms ----
        {
            const int arow = wbase + (lane & 15);
            const int acolh = ((lane >> 4) & 1) * 16;
            const int brow_base = lane & 7;
            const int bcolh = ((lane >> 3) & 1) * 16;
            #pragma unroll
            for (int ks = 0; ks < 4; ks++) {
                uint32_t Afh[4], Afl[4];
                uint32_t aoff = SWB(arow, ks*32 + acolh);
                ldsm_x4(Afh, ahi_u + aoff);
                ldsm_x4(Afl, alo_u + aoff);
                #pragma unroll
                for (int nt = 0; nt < 8; nt++) {
                    const int brow = nt*8 + brow_base;
                    uint32_t boff = SWB(brow, ks*32 + bcolh);
                    uint32_t Bfh[2], Bfl[2];
                    ldsm_x2(Bfh, bhi_u + boff);
                    ldsm_x2(Bfl, blo_u + boff);
                    mma16816(C[nt], Afh, Bfh);
                    mma16816(C[nt], Afl, Bfh);
                    mma16816(C[nt], Afh, Bfl);
                }
            }
        }
    }

    // ---- epilogue: C fragment -> out[b][o][h][w] ----
    {
        const int g = lane >> 2, t = lane & 3;
        const int m0 = wbase + g;
        float* ob = out + (size_t)b*CO_*HW_ + h*W_;
        #pragma unroll
        for (int nt = 0; nt < 8; nt++) {
            const int n0 = nt*8 + 2*t;
            ob[(size_t)n0*HW_ + m0]         = C[nt][0];
            ob[(size_t)(n0+1)*HW_ + m0]     = C[nt][1];
            ob[(size_t)n0*HW_ + m0 + 8]     = C[nt][2];
            ob[(size_t)(n0+1)*HW_ + m0 + 8] = C[nt][3];
        }
    }
}

extern "C" void kernel_launch(void* const* d_in, const int* in_sizes, int n_in,
                              void* d_out, int out_size) {
    const float* mem   = (const float*)d_in[0];
    const float* que   = (const float*)d_in[1];
    const float* w_off = (const float*)d_in[2];
    const float* b_off = (const float*)d_in[3];
    const float* w_def = (const float*)d_in[4];
    float* out = (float*)d_out;

    prep_weights_kernel<<<(N_WOFF + N_WB + 255)/256, 256>>>(w_off, w_def);
    transpose_mem_kernel<<<B_*H_, 256>>>(mem);
    offset_conv_kernel<<<B_*H_/2, 128>>>(mem, que, b_off);
    deform_mma_kernel<<<B_*H_, 256>>>(out);
}

// round 11
// speedup vs baseline: 1.6104x; 1.3390x over previous
#include <cuda_runtime.h>
#include <cuda_bf16.h>
#include <cstdint>

typedef unsigned long long u64;

#define B_    8
#define CM_   64
#define CQ_   64
#define CIN_  128
#define CO_   64
#define H_    128
#define W_    128
#define K_    9
#define JOFF_ 27
#define HW_   (H_*W_)

// Scratch (no cudaMalloc allowed).
__device__ __align__(16) float  g_off[B_*JOFF_*HW_];      // [b][j][h][w]
__device__ __align__(16) __nv_bfloat16 g_wbf[K_*2*4096];  // deform W: [tap][hi|lo][n][k]
__device__ __align__(16) __nv_bfloat16 g_wobf[K_*2*2*2048]; // offset W: [tap][half][hi|lo][n=32][k=64]
__device__ __align__(16) float  g_xT[B_*HW_*CIN_];        // channel-last concat [b][h][w][c=128]

__device__ __forceinline__ uint32_t smem_u32(const void* p) {
    uint32_t a;
    asm("{ .reg .u64 t; cvta.to.shared.u64 t, %1; cvt.u32.u64 %0, t; }" : "=r"(a) : "l"(p));
    return a;
}

#define SWB(row, colb) ((row)*128 + ((((colb) >> 4) ^ ((row) & 7)) << 4) + ((colb) & 15))

__device__ __forceinline__ void ldsm_x4(uint32_t a[4], uint32_t addr) {
    asm volatile("ldmatrix.sync.aligned.m8n8.x4.shared.b16 {%0,%1,%2,%3}, [%4];"
        : "=r"(a[0]), "=r"(a[1]), "=r"(a[2]), "=r"(a[3]) : "r"(addr));
}
__device__ __forceinline__ void ldsm_x2(uint32_t b[2], uint32_t addr) {
    asm volatile("ldmatrix.sync.aligned.m8n8.x2.shared.b16 {%0,%1}, [%2];"
        : "=r"(b[0]), "=r"(b[1]) : "r"(addr));
}
__device__ __forceinline__ void mma16816(float c[4], const uint32_t a[4], const uint32_t b[2]) {
    asm volatile("mma.sync.aligned.m16n8k16.row.col.f32.bf16.bf16.f32 "
        "{%0,%1,%2,%3}, {%4,%5,%6,%7}, {%8,%9}, {%0,%1,%2,%3};"
        : "+f"(c[0]), "+f"(c[1]), "+f"(c[2]), "+f"(c[3])
        : "r"(a[0]), "r"(a[1]), "r"(a[2]), "r"(a[3]), "r"(b[0]), "r"(b[1]));
}

// split fp32 -> bf16 hi + residual lo
__device__ __forceinline__ void bf16split(float s, uint16_t &hi, uint16_t &lo) {
    __nv_bfloat16 h = __float2bfloat16_rn(s);
    __nv_bfloat16 l = __float2bfloat16_rn(s - __bfloat162float(h));
    hi = __bfloat16_as_ushort(h);
    lo = __bfloat16_as_ushort(l);
}

// ---------------------------------------------------------------------------
// Prep: deform weights (bf16 hi/lo [n][k]) + offset weights
// ([tap][half][hi|lo][n=32 pad][k=64]).
// ---------------------------------------------------------------------------
#define N_WB   (K_*64*64)       // 36864
#define N_WO   (K_*2*32*64)     // 36864
__global__ void prep_weights_kernel(const float* __restrict__ w_off,
                                    const float* __restrict__ w_def) {
    int i = blockIdx.x * 256 + threadIdx.x;
    if (i < N_WB) {
        int tap = i / 4096;
        int r = i - tap*4096;
        int n = r >> 6;
        int c = r & 63;
        float w = w_def[(n*CM_ + c)*K_ + tap];
        __nv_bfloat16 hi = __float2bfloat16_rn(w);
        __nv_bfloat16 lo = __float2bfloat16_rn(w - __bfloat162float(hi));
        g_wbf[tap*8192 + n*64 + c]        = hi;
        g_wbf[tap*8192 + 4096 + n*64 + c] = lo;
    } else if (i < N_WB + N_WO) {
        int i2 = i - N_WB;
        int tap = i2 / 4096;
        int r = i2 - tap*4096;
        int half = r >> 11;
        int r2 = r & 2047;
        int n = r2 >> 6;
        int k = r2 & 63;
        int c = half*64 + k;
        float w = (n < JOFF_) ? w_off[(n*CIN_ + c)*K_ + tap] : 0.f;
        __nv_bfloat16 hi = __float2bfloat16_rn(w);
        __nv_bfloat16 lo = __float2bfloat16_rn(w - __bfloat162float(hi));
        g_wobf[tap*8192 + half*4096 + n*64 + k]        = hi;
        g_wobf[tap*8192 + half*4096 + 2048 + n*64 + k] = lo;
    }
}

// ---------------------------------------------------------------------------
// Transpose concat(mem,que) -> channel-last g_xT[b][h][w][c=128].
// ---------------------------------------------------------------------------
__global__ __launch_bounds__(256) void transpose_x_kernel(
        const float* __restrict__ mem, const float* __restrict__ que) {
    __shared__ float tile[64][129];
    const int bh = blockIdx.x;
    const int b = bh >> 7, h = bh & 127;
    const int tid = threadIdx.x;
    #pragma unroll
    for (int pass = 0; pass < 2; pass++) {
        const float* src = (pass ? que + (size_t)b*CQ_*HW_ : mem + (size_t)b*CM_*HW_) + h*W_;
        #pragma unroll
        for (int m = 0; m < 32; m++) {
            int e = tid + 256*m;
            int c = e >> 7, w = e & 127;
            tile[c][w] = src[(size_t)c*HW_ + w];
        }
        __syncthreads();
        float* dst = g_xT + ((size_t)b*HW_ + h*W_)*CIN_ + pass*64;
        #pragma unroll
        for (int m = 0; m < 32; m++) {
            int e = tid + 256*m;
            int w = e >> 6, c = e & 63;
            dst[(size_t)w*CIN_ + c] = tile[c][w];
        }
        __syncthreads();
    }
}

// ---------------------------------------------------------------------------
// Offset conv on mma.sync: 3x3 conv = 9 shifted 1x1 GEMMs.
// Block = one (b,h) row, 8 warps; warp w owns pixels 16w..15. 18 stages
// (9 taps x 2 channel-halves): stage A[128px x 64ch] (shifted contiguous
// rows of g_xT, bf16 hi/lo) + B tile; 4 ks x 4 nt x 3 split-term MMAs.
// ---------------------------------------------------------------------------
__global__ __launch_bounds__(256) void offset_mma_kernel(const float* __restrict__ b_off) {
    __shared__ __align__(16) char smem[40960];   // Ahi 16K | Alo 16K | Bhi 4K | Blo 4K
    char* Ahi = smem;
    char* Alo = smem + 16384;
    char* Bhi = smem + 32768;
    char* Blo = smem + 36864;
    const uint32_t ahi_u = smem_u32(Ahi), alo_u = smem_u32(Alo);
    const uint32_t bhi_u = smem_u32(Bhi), blo_u = smem_u32(Blo);

    const int tid  = threadIdx.x;
    const int lane = tid & 31;
    const int wrp  = tid >> 5;
    const int bh   = blockIdx.x;
    const int b    = bh >> 7;
    const int h    = bh & 127;
    const int wbase = wrp * 16;
    const int chunk = lane & 15;

    const char* xTb = (const char*)(g_xT + (size_t)b*HW_*CIN_);

    float C[4][4];
    #pragma unroll
    for (int nt = 0; nt < 4; nt++)
        #pragma unroll
        for (int i = 0; i < 4; i++) C[nt][i] = 0.f;

    for (int st = 0; st < 18; st++) {
        const int tap = st >> 1;
        const int hh  = st & 1;             // channel half
        const int ky  = tap / 3, kx = tap - ky*3;
        const int rowv = h + ky - 1;
        const bool rowok = (rowv >= 0 && rowv < H_);

        __syncthreads();   // previous stage's MMAs done

        // ---- stage B (4KB hi + 4KB lo), swizzled ----
        {
            const uint4* src = (const uint4*)(g_wobf + (size_t)tap*8192 + hh*4096);
            uint4 vh = src[tid];
            uint4 vl = src[256 + tid];
            int n = tid >> 3, kc = tid & 7;
            uint32_t doff = n*128 + ((kc ^ (n & 7)) << 4);
            *(uint4*)(Bhi + doff) = vh;
            *(uint4*)(Blo + doff) = vl;
        }

        // ---- stage A: shifted contiguous copy, bf16 hi/lo ----
        {
            const char* xrow = xTb + ((size_t)rowv*W_)*512 + hh*256;
            #pragma unroll
            for (int i = 0; i < 8; i++) {
                const int sub = 2*i + (lane >> 4);
                const int px  = wbase + sub;
                const int ww  = px + kx - 1;
                float4 v = make_float4(0.f, 0.f, 0.f, 0.f);
                if (rowok && ww >= 0 && ww < W_)
                    v = *(const float4*)(xrow + (size_t)ww*512 + chunk*16);
                uint16_t h0,h1,h2,h3,l0,l1,l2,l3;
                bf16split(v.x, h0, l0);
                bf16split(v.y, h1, l1);
                bf16split(v.z, h2, l2);
                bf16split(v.w, h3, l3);
                u64 hiq = ((u64)h3 << 48) | ((u64)h2 << 32) | ((u64)h1 << 16) | h0;
                u64 loq = ((u64)l3 << 48) | ((u64)l2 << 32) | ((u64)l1 << 16) | l0;
                const uint32_t off = SWB(px, chunk*8);
                *(u64*)(Ahi + off) = hiq;
                *(u64*)(Alo + off) = loq;
            }
        }
        __syncthreads();   // A + B ready everywhere

        // ---- MMA: 4 k-steps x 4 n-tiles x 3 split terms ----
        {
            const int arow = wbase + (lane & 15);
            const int acolh = ((lane >> 4) & 1) * 16;
            const int brow_base = lane & 7;
            const int bcolh = ((lane >> 3) & 1) * 16;
            #pragma unroll
            for (int ks = 0; ks < 4; ks++) {
                uint32_t Afh[4], Afl[4];
                uint32_t aoff = SWB(arow, ks*32 + acolh);
                ldsm_x4(Afh, ahi_u + aoff);
                ldsm_x4(Afl, alo_u + aoff);
                #pragma unroll
                for (int nt = 0; nt < 4; nt++) {
                    const int brow = nt*8 + brow_base;
                    uint32_t boff = SWB(brow, ks*32 + bcolh);
                    uint32_t Bfh[2], Bfl[2];
                    ldsm_x2(Bfh, bhi_u + boff);
                    ldsm_x2(Bfl, blo_u + boff);
                    mma16816(C[nt], Afh, Bfh);
                    mma16816(C[nt], Afl, Bfh);
                    mma16816(C[nt], Afh, Bfl);
                }
            }
        }
    }

    // ---- epilogue: C + bias -> g_off[b][j][h][w], j < 27 ----
    {
        const int g = lane >> 2, t4 = lane & 3;
        const int m0 = wbase + g;
        float* ob = g_off + (size_t)b*JOFF_*HW_ + h*W_;
        #pragma unroll
        for (int nt = 0; nt < 4; nt++) {
            const int n0 = nt*8 + 2*t4;
            if (n0 < JOFF_) {
                float bi = b_off[n0];
                ob[(size_t)n0*HW_ + m0]     = C[nt][0] + bi;
                ob[(size_t)n0*HW_ + m0 + 8] = C[nt][2] + bi;
            }
            if (n0 + 1 < JOFF_) {
                float bi = b_off[n0 + 1];
                ob[(size_t)(n0+1)*HW_ + m0]     = C[nt][1] + bi;
                ob[(size_t)(n0+1)*HW_ + m0 + 8] = C[nt][3] + bi;
            }
        }
    }
}

// ---------------------------------------------------------------------------
// Deformable conv, mma.sync + channel-last gather (validated R9), now on g_xT.
// ---------------------------------------------------------------------------
__global__ __launch_bounds__(256) void deform_mma_kernel(float* __restrict__ out) {
    __shared__ __align__(16) char smem[49152];   // Ahi 16K | Alo 16K | Bhi 8K | Blo 8K
    char* Ahi = smem;
    char* Alo = smem + 16384;
    char* Bhi = smem + 32768;
    char* Blo = smem + 40960;
    const uint32_t ahi_u = smem_u32(Ahi), alo_u = smem_u32(Alo);
    const uint32_t bhi_u = smem_u32(Bhi), blo_u = smem_u32(Blo);

    const int tid  = threadIdx.x;
    const int lane = tid & 31;
    const int wrp  = tid >> 5;
    const int bh   = blockIdx.x;
    const int b    = bh >> 7;
    const int h    = bh & 127;
    const int wbase = wrp * 16;
    const int chunk = lane & 15;

    const char* memTb = (const char*)(g_xT + (size_t)b*HW_*CIN_);  // ch 0-63 = mem
    const float* offrow = g_off + (size_t)b*JOFF_*HW_ + h*W_;

    float C[8][4];
    #pragma unroll
    for (int nt = 0; nt < 8; nt++)
        #pragma unroll
        for (int i = 0; i < 4; i++) C[nt][i] = 0.f;

    for (int tap = 0; tap < K_; tap++) {
        __syncthreads();

        // ---- stage B[tap] (hi 8KB + lo 8KB), swizzled ----
        {
            const uint4* src = (const uint4*)(g_wbf + (size_t)tap*8192);
            #pragma unroll
            for (int m = 0; m < 4; m++) {
                int e = tid + 256*m;
                uint4 v = src[e];
                int e2 = e & 511;
                int n = e2 >> 3, kc = e2 & 7;
                char* dst = (e < 512) ? Bhi : Blo;
                *(uint4*)(dst + n*128 + ((kc ^ (n & 7)) << 4)) = v;
            }
        }

        // ---- per-warp bilinear params (lanes' px = wbase + (lane&15)) ----
        float W00, W01, W10, W11;
        int   B00, B01, B10, B11;
        {
            const int ppx = wbase + (lane & 15);
            const float* op = offrow + ppx;
            float dy  = op[(2*tap)*HW_];
            float dx  = op[(2*tap+1)*HW_];
            float msk = op[(18+tap)*HW_];
            float py  = (float)(h + (tap/3) - 1) + dy;
            float pxx = (float)(ppx + (tap - (tap/3)*3) - 1) + dx;
            float y0f = floorf(py), x0f = floorf(pxx);
            float fy = py - y0f, fx = pxx - x0f;
            int y0 = (int)y0f, x0 = (int)x0f;
            int y1 = y0 + 1,   x1 = x0 + 1;
            float vy0 = (y0 >= 0 && y0 < H_) ? 1.f : 0.f;
            float vy1 = (y1 >= 0 && y1 < H_) ? 1.f : 0.f;
            float vx0 = (x0 >= 0 && x0 < W_) ? 1.f : 0.f;
            float vx1 = (x1 >= 0 && x1 < W_) ? 1.f : 0.f;
            int y0c = min(max(y0, 0), H_-1), y1c = min(max(y1, 0), H_-1);
            int x0c = min(max(x0, 0), W_-1), x1c = min(max(x1, 0), W_-1);
            W00 = (1.f-fy)*(1.f-fx)*msk*vy0*vx0;
            W01 = (1.f-fy)*fx      *msk*vy0*vx1;
            W10 = fy      *(1.f-fx)*msk*vy1*vx0;
            W11 = fy      *fx      *msk*vy1*vx1;
            B00 = (y0c*W_ + x0c) << 9;    // *512B (128 ch x 4B per pixel)
            B01 = (y0c*W_ + x1c) << 9;
            B10 = (y1c*W_ + x0c) << 9;
            B11 = (y1c*W_ + x1c) << 9;
        }

        __syncthreads();

        // ---- gather: 8 iters x 2 pixels; lane = 16B channel chunk ----
        #pragma unroll
        for (int i = 0; i < 8; i++) {
            const int sub = 2*i + (lane >> 4);
            float w00 = __shfl_sync(0xffffffffu, W00, sub);
            float w01 = __shfl_sync(0xffffffffu, W01, sub);
            float w10 = __shfl_sync(0xffffffffu, W10, sub);
            float w11 = __shfl_sync(0xffffffffu, W11, sub);
            int   b00 = __shfl_sync(0xffffffffu, B00, sub);
            int   b01 = __shfl_sync(0xffffffffu, B01, sub);
            int   b10 = __shfl_sync(0xffffffffu, B10, sub);
            int   b11 = __shfl_sync(0xffffffffu, B11, sub);
            const int cb = chunk * 16;
            float4 c00 = *(const float4*)(memTb + b00 + cb);
            float4 c01 = *(const float4*)(memTb + b01 + cb);
            float4 c10 = *(const float4*)(memTb + b10 + cb);
            float4 c11 = *(const float4*)(memTb + b11 + cb);
            float s0 = w00*c00.x + w01*c01.x + w10*c10.x + w11*c11.x;
            float s1 = w00*c00.y + w01*c01.y + w10*c10.y + w11*c11.y;
            float s2 = w00*c00.z + w01*c01.z + w10*c10.z + w11*c11.z;
            float s3 = w00*c00.w + w01*c01.w + w10*c10.w + w11*c11.w;
            uint16_t h0,h1,h2,h3,l0,l1,l2,l3;
            bf16split(s0, h0, l0);
            bf16split(s1, h1, l1);
            bf16split(s2, h2, l2);
            bf16split(s3, h3, l3);
            u64 hiq = ((u64)h3 << 48) | ((u64)h2 << 32) | ((u64)h1 << 16) | h0;
            u64 loq = ((u64)l3 << 48) | ((u64)l2 << 32) | ((u64)l1 << 16) | l0;
            const int px = wbase + sub;
            const uint32_t off = SWB(px, chunk*8);
            *(u64*)(Ahi + off) = hiq;
            *(u64*)(Alo + off) = loq;
        }
        __syncwarp();   // A tile is warp-private

        // ---- MMA: 4 k-steps x 8 n-tiles x 3 split terms ----
        {
            const int arow = wbase + (lane & 15);
            const int acolh = ((lane >> 4) & 1) * 16;
            const int brow_base = lane & 7;
            const int bcolh = ((lane >> 3) & 1) * 16;
            #pragma unroll
            for (int ks = 0; ks < 4; ks++) {
                uint32_t Afh[4], Afl[4];
                uint32_t aoff = SWB(arow, ks*32 + acolh);
                ldsm_x4(Afh, ahi_u + aoff);
                ldsm_x4(Afl, alo_u + aoff);
                #pragma unroll
                for (int nt = 0; nt < 8; nt++) {
                    const int brow = nt*8 + brow_base;
                    uint32_t boff = SWB(brow, ks*32 + bcolh);
                    uint32_t Bfh[2], Bfl[2];
                    ldsm_x2(Bfh, bhi_u + boff);
                    ldsm_x2(Bfl, blo_u + boff);
                    mma16816(C[nt], Afh, Bfh);
                    mma16816(C[nt], Afl, Bfh);
                    mma16816(C[nt], Afh, Bfl);
                }
            }
        }
    }

    // ---- epilogue: C fragment -> out[b][o][h][w] ----
    {
        const int g = lane >> 2, t = lane & 3;
        const int m0 = wbase + g;
        float* ob = out + (size_t)b*CO_*HW_ + h*W_;
        #pragma unroll
        for (int nt = 0; nt < 8; nt++) {
            const int n0 = nt*8 + 2*t;
            ob[(size_t)n0*HW_ + m0]         = C[nt][0];
            ob[(size_t)(n0+1)*HW_ + m0]     = C[nt][1];
            ob[(size_t)n0*HW_ + m0 + 8]     = C[nt][2];
            ob[(size_t)(n0+1)*HW_ + m0 + 8] = C[nt][3];
        }
    }
}

extern "C" void kernel_launch(void* const* d_in, const int* in_sizes, int n_in,
                              void* d_out, int out_size) {
    const float* mem   = (const float*)d_in[0];
    const float* que   = (const float*)d_in[1];
    const float* w_off = (const float*)d_in[2];
    const float* b_off = (const float*)d_in[3];
    const float* w_def = (const float*)d_in[4];
    float* out = (float*)d_out;

    prep_weights_kernel<<<(N_WB + N_WO + 255)/256, 256>>>(w_off, w_def);
    transpose_x_kernel<<<B_*H_, 256>>>(mem, que);
    offset_mma_kernel<<<B_*H_, 256>>>(b_off);
    deform_mma_kernel<<<B_*H_, 256>>>(out);
}

// round 12
// speedup vs baseline: 1.7865x; 1.1094x over previous
#include <cuda_runtime.h>
#include <cuda_bf16.h>
#include <cstdint>

typedef unsigned long long u64;

#define B_    8
#define CM_   64
#define CQ_   64
#define CIN_  128
#define CO_   64
#define H_    128
#define W_    128
#define K_    9
#define JOFF_ 27
#define HW_   (H_*W_)

// Scratch (no cudaMalloc allowed).
__device__ __align__(16) float  g_off[B_*JOFF_*HW_];      // [b][j][h][w]
__device__ __align__(16) __nv_bfloat16 g_wbf[K_*2*4096];  // deform W: [tap][hi|lo][n][k]
__device__ __align__(16) __nv_bfloat16 g_wobf[K_*2*2*2048]; // offset W: [tap][half][hi|lo][n=32][k=64]
__device__ __align__(16) float  g_xT[B_*HW_*CIN_];        // channel-last concat [b][h][w][c=128]

__device__ __forceinline__ uint32_t smem_u32(const void* p) {
    uint32_t a;
    asm("{ .reg .u64 t; cvta.to.shared.u64 t, %1; cvt.u32.u64 %0, t; }" : "=r"(a) : "l"(p));
    return a;
}

#define SWB(row, colb) ((row)*128 + ((((colb) >> 4) ^ ((row) & 7)) << 4) + ((colb) & 15))

__device__ __forceinline__ void ldsm_x4(uint32_t a[4], uint32_t addr) {
    asm volatile("ldmatrix.sync.aligned.m8n8.x4.shared.b16 {%0,%1,%2,%3}, [%4];"
        : "=r"(a[0]), "=r"(a[1]), "=r"(a[2]), "=r"(a[3]) : "r"(addr));
}
__device__ __forceinline__ void ldsm_x2(uint32_t b[2], uint32_t addr) {
    asm volatile("ldmatrix.sync.aligned.m8n8.x2.shared.b16 {%0,%1}, [%2];"
        : "=r"(b[0]), "=r"(b[1]) : "r"(addr));
}
__device__ __forceinline__ void mma16816(float c[4], const uint32_t a[4], const uint32_t b[2]) {
    asm volatile("mma.sync.aligned.m16n8k16.row.col.f32.bf16.bf16.f32 "
        "{%0,%1,%2,%3}, {%4,%5,%6,%7}, {%8,%9}, {%0,%1,%2,%3};"
        : "+f"(c[0]), "+f"(c[1]), "+f"(c[2]), "+f"(c[3])
        : "r"(a[0]), "r"(a[1]), "r"(a[2]), "r"(a[3]), "r"(b[0]), "r"(b[1]));
}

// split fp32 -> bf16 hi + residual lo
__device__ __forceinline__ void bf16split(float s, uint16_t &hi, uint16_t &lo) {
    __nv_bfloat16 h = __float2bfloat16_rn(s);
    __nv_bfloat16 l = __float2bfloat16_rn(s - __bfloat162float(h));
    hi = __bfloat16_as_ushort(h);
    lo = __bfloat16_as_ushort(l);
}

// ---------------------------------------------------------------------------
// Prep: deform weights (bf16 hi/lo [n][k]) + offset weights
// ([tap][half][hi|lo][n=32 pad][k=64]).
// ---------------------------------------------------------------------------
#define N_WB   (K_*64*64)       // 36864
#define N_WO   (K_*2*32*64)     // 36864
__global__ void prep_weights_kernel(const float* __restrict__ w_off,
                                    const float* __restrict__ w_def) {
    int i = blockIdx.x * 256 + threadIdx.x;
    if (i < N_WB) {
        int tap = i / 4096;
        int r = i - tap*4096;
        int n = r >> 6;
        int c = r & 63;
        float w = w_def[(n*CM_ + c)*K_ + tap];
        __nv_bfloat16 hi = __float2bfloat16_rn(w);
        __nv_bfloat16 lo = __float2bfloat16_rn(w - __bfloat162float(hi));
        g_wbf[tap*8192 + n*64 + c]        = hi;
        g_wbf[tap*8192 + 4096 + n*64 + c] = lo;
    } else if (i < N_WB + N_WO) {
        int i2 = i - N_WB;
        int tap = i2 / 4096;
        int r = i2 - tap*4096;
        int half = r >> 11;
        int r2 = r & 2047;
        int n = r2 >> 6;
        int k = r2 & 63;
        int c = half*64 + k;
        float w = (n < JOFF_) ? w_off[(n*CIN_ + c)*K_ + tap] : 0.f;
        __nv_bfloat16 hi = __float2bfloat16_rn(w);
        __nv_bfloat16 lo = __float2bfloat16_rn(w - __bfloat162float(hi));
        g_wobf[tap*8192 + half*4096 + n*64 + k]        = hi;
        g_wobf[tap*8192 + half*4096 + 2048 + n*64 + k] = lo;
    }
}

// ---------------------------------------------------------------------------
// Transpose concat(mem,que) -> channel-last g_xT[b][h][w][c=128].
// ---------------------------------------------------------------------------
__global__ __launch_bounds__(256) void transpose_x_kernel(
        const float* __restrict__ mem, const float* __restrict__ que) {
    __shared__ float tile[64][129];
    const int bh = blockIdx.x;
    const int b = bh >> 7, h = bh & 127;
    const int tid = threadIdx.x;
    #pragma unroll
    for (int pass = 0; pass < 2; pass++) {
        const float* src = (pass ? que + (size_t)b*CQ_*HW_ : mem + (size_t)b*CM_*HW_) + h*W_;
        #pragma unroll
        for (int m = 0; m < 32; m++) {
            int e = tid + 256*m;
            int c = e >> 7, w = e & 127;
            tile[c][w] = src[(size_t)c*HW_ + w];
        }
        __syncthreads();
        float* dst = g_xT + ((size_t)b*HW_ + h*W_)*CIN_ + pass*64;
        #pragma unroll
        for (int m = 0; m < 32; m++) {
            int e = tid + 256*m;
            int w = e >> 6, c = e & 63;
            dst[(size_t)w*CIN_ + c] = tile[c][w];
        }
        __syncthreads();
    }
}

// ---------------------------------------------------------------------------
// Offset conv on mma.sync: 3x3 conv = 9 shifted 1x1 GEMMs. 18 stages.
// B LDGs issued before sync1 (fly under previous stage's MMA drain);
// A tile is warp-private (own rows only) -> staged between the two syncs.
// ---------------------------------------------------------------------------
__global__ __launch_bounds__(256, 3) void offset_mma_kernel(const float* __restrict__ b_off) {
    __shared__ __align__(16) char smem[40960];   // Ahi 16K | Alo 16K | Bhi 4K | Blo 4K
    char* Ahi = smem;
    char* Alo = smem + 16384;
    char* Bhi = smem + 32768;
    char* Blo = smem + 36864;
    const uint32_t ahi_u = smem_u32(Ahi), alo_u = smem_u32(Alo);
    const uint32_t bhi_u = smem_u32(Bhi), blo_u = smem_u32(Blo);

    const int tid  = threadIdx.x;
    const int lane = tid & 31;
    const int wrp  = tid >> 5;
    const int bh   = blockIdx.x;
    const int b    = bh >> 7;
    const int h    = bh & 127;
    const int wbase = wrp * 16;
    const int chunk = lane & 15;

    const char* xTb = (const char*)(g_xT + (size_t)b*HW_*CIN_);

    float C[4][4];
    #pragma unroll
    for (int nt = 0; nt < 4; nt++)
        #pragma unroll
        for (int i = 0; i < 4; i++) C[nt][i] = 0.f;

    for (int st = 0; st < 18; st++) {
        const int tap = st >> 1;
        const int hh  = st & 1;             // channel half
        const int ky  = tap / 3, kx = tap - ky*3;
        const int rowv = h + ky - 1;
        const bool rowok = (rowv >= 0 && rowv < H_);

        // ---- B LDGs early (fly under previous MMA drain) ----
        const uint4* bsrc = (const uint4*)(g_wobf + (size_t)tap*8192 + hh*4096);
        uint4 vh = bsrc[tid];
        uint4 vl = bsrc[256 + tid];

        __syncthreads();   // previous stage's MMAs done; smem writable

        // ---- STS B (swizzled) ----
        {
            int n = tid >> 3, kc = tid & 7;
            uint32_t doff = n*128 + ((kc ^ (n & 7)) << 4);
            *(uint4*)(Bhi + doff) = vh;
            *(uint4*)(Blo + doff) = vl;
        }

        // ---- stage A: shifted contiguous copy, bf16 hi/lo (warp-private) ----
        {
            const char* xrow = xTb + ((size_t)rowv*W_)*512 + hh*256;
            #pragma unroll
            for (int i = 0; i < 8; i++) {
                const int sub = 2*i + (lane >> 4);
                const int px  = wbase + sub;
                const int ww  = px + kx - 1;
                float4 v = make_float4(0.f, 0.f, 0.f, 0.f);
                if (rowok && ww >= 0 && ww < W_)
                    v = *(const float4*)(xrow + (size_t)ww*512 + chunk*16);
                uint16_t h0,h1,h2,h3,l0,l1,l2,l3;
                bf16split(v.x, h0, l0);
                bf16split(v.y, h1, l1);
                bf16split(v.z, h2, l2);
                bf16split(v.w, h3, l3);
                u64 hiq = ((u64)h3 << 48) | ((u64)h2 << 32) | ((u64)h1 << 16) | h0;
                u64 loq = ((u64)l3 << 48) | ((u64)l2 << 32) | ((u64)l1 << 16) | l0;
                const uint32_t off = SWB(px, chunk*8);
                *(u64*)(Ahi + off) = hiq;
                *(u64*)(Alo + off) = loq;
            }
        }
        __syncthreads();   // B visible everywhere; own A done

        // ---- MMA: 4 k-steps x 4 n-tiles x 3 split terms ----
        {
            const int arow = wbase + (lane & 15);
            const int acolh = ((lane >> 4) & 1) * 16;
            const int brow_base = lane & 7;
            const int bcolh = ((lane >> 3) & 1) * 16;
            #pragma unroll
            for (int ks = 0; ks < 4; ks++) {
                uint32_t Afh[4], Afl[4];
                uint32_t aoff = SWB(arow, ks*32 + acolh);
                ldsm_x4(Afh, ahi_u + aoff);
                ldsm_x4(Afl, alo_u + aoff);
                #pragma unroll
                for (int nt = 0; nt < 4; nt++) {
                    const int brow = nt*8 + brow_base;
                    uint32_t boff = SWB(brow, ks*32 + bcolh);
                    uint32_t Bfh[2], Bfl[2];
                    ldsm_x2(Bfh, bhi_u + boff);
                    ldsm_x2(Bfl, blo_u + boff);
                    mma16816(C[nt], Afh, Bfh);
                    mma16816(C[nt], Afl, Bfh);
                    mma16816(C[nt], Afh, Bfl);
                }
            }
        }
    }

    // ---- epilogue: C + bias -> g_off[b][j][h][w], j < 27 ----
    {
        const int g = lane >> 2, t4 = lane & 3;
        const int m0 = wbase + g;
        float* ob = g_off + (size_t)b*JOFF_*HW_ + h*W_;
        #pragma unroll
        for (int nt = 0; nt < 4; nt++) {
            const int n0 = nt*8 + 2*t4;
            if (n0 < JOFF_) {
                float bi = b_off[n0];
                ob[(size_t)n0*HW_ + m0]     = C[nt][0] + bi;
                ob[(size_t)n0*HW_ + m0 + 8] = C[nt][2] + bi;
            }
            if (n0 + 1 < JOFF_) {
                float bi = b_off[n0 + 1];
                ob[(size_t)(n0+1)*HW_ + m0]     = C[nt][1] + bi;
                ob[(size_t)(n0+1)*HW_ + m0 + 8] = C[nt][3] + bi;
            }
        }
    }
}

// ---------------------------------------------------------------------------
// Deformable conv, mma.sync + channel-last gather. Params + B LDGs issued
// before sync1; gather (warp-private A) between syncs; one sync before MMA.
// ---------------------------------------------------------------------------
__global__ __launch_bounds__(256, 3) void deform_mma_kernel(float* __restrict__ out) {
    __shared__ __align__(16) char smem[49152];   // Ahi 16K | Alo 16K | Bhi 8K | Blo 8K
    char* Ahi = smem;
    char* Alo = smem + 16384;
    char* Bhi = smem + 32768;
    char* Blo = smem + 40960;
    const uint32_t ahi_u = smem_u32(Ahi), alo_u = smem_u32(Alo);
    const uint32_t bhi_u = smem_u32(Bhi), blo_u = smem_u32(Blo);

    const int tid  = threadIdx.x;
    const int lane = tid & 31;
    const int wrp  = tid >> 5;
    const int bh   = blockIdx.x;
    const int b    = bh >> 7;
    const int h    = bh & 127;
    const int wbase = wrp * 16;
    const int chunk = lane & 15;

    const char* memTb = (const char*)(g_xT + (size_t)b*HW_*CIN_);  // ch 0-63 = mem
    const float* offrow = g_off + (size_t)b*JOFF_*HW_ + h*W_;

    float C[8][4];
    #pragma unroll
    for (int nt = 0; nt < 8; nt++)
        #pragma unroll
        for (int i = 0; i < 4; i++) C[nt][i] = 0.f;

    for (int tap = 0; tap < K_; tap++) {
        // ---- per-warp bilinear params (no smem; LDGs fly under prev MMA) ----
        float W00, W01, W10, W11;
        int   B00, B01, B10, B11;
        {
            const int ppx = wbase + (lane & 15);
            const float* op = offrow + ppx;
            float dy  = op[(2*tap)*HW_];
            float dx  = op[(2*tap+1)*HW_];
            float msk = op[(18+tap)*HW_];
            float py  = (float)(h + (tap/3) - 1) + dy;
            float pxx = (float)(ppx + (tap - (tap/3)*3) - 1) + dx;
            float y0f = floorf(py), x0f = floorf(pxx);
            float fy = py - y0f, fx = pxx - x0f;
            int y0 = (int)y0f, x0 = (int)x0f;
            int y1 = y0 + 1,   x1 = x0 + 1;
            float vy0 = (y0 >= 0 && y0 < H_) ? 1.f : 0.f;
            float vy1 = (y1 >= 0 && y1 < H_) ? 1.f : 0.f;
            float vx0 = (x0 >= 0 && x0 < W_) ? 1.f : 0.f;
            float vx1 = (x1 >= 0 && x1 < W_) ? 1.f : 0.f;
            int y0c = min(max(y0, 0), H_-1), y1c = min(max(y1, 0), H_-1);
            int x0c = min(max(x0, 0), W_-1), x1c = min(max(x1, 0), W_-1);
            W00 = (1.f-fy)*(1.f-fx)*msk*vy0*vx0;
            W01 = (1.f-fy)*fx      *msk*vy0*vx1;
            W10 = fy      *(1.f-fx)*msk*vy1*vx0;
            W11 = fy      *fx      *msk*vy1*vx1;
            B00 = (y0c*W_ + x0c) << 9;    // *512B (128 ch x 4B per pixel)
            B01 = (y0c*W_ + x1c) << 9;
            B10 = (y1c*W_ + x0c) << 9;
            B11 = (y1c*W_ + x1c) << 9;
        }

        // ---- B LDGs early ----
        const uint4* bsrc = (const uint4*)(g_wbf + (size_t)tap*8192);
        uint4 bv[4];
        #pragma unroll
        for (int m = 0; m < 4; m++) bv[m] = bsrc[tid + 256*m];

        __syncthreads();   // previous tap's MMAs done; smem writable

        // ---- STS B (swizzled) ----
        #pragma unroll
        for (int m = 0; m < 4; m++) {
            int e = tid + 256*m;
            int e2 = e & 511;
            int n = e2 >> 3, kc = e2 & 7;
            char* dst = (e < 512) ? Bhi : Blo;
            *(uint4*)(dst + n*128 + ((kc ^ (n & 7)) << 4)) = bv[m];
        }

        // ---- gather: 8 iters x 2 pixels; lane = 16B channel chunk ----
        #pragma unroll
        for (int i = 0; i < 8; i++) {
            const int sub = 2*i + (lane >> 4);
            float w00 = __shfl_sync(0xffffffffu, W00, sub);
            float w01 = __shfl_sync(0xffffffffu, W01, sub);
            float w10 = __shfl_sync(0xffffffffu, W10, sub);
            float w11 = __shfl_sync(0xffffffffu, W11, sub);
            int   b00 = __shfl_sync(0xffffffffu, B00, sub);
            int   b01 = __shfl_sync(0xffffffffu, B01, sub);
            int   b10 = __shfl_sync(0xffffffffu, B10, sub);
            int   b11 = __shfl_sync(0xffffffffu, B11, sub);
            const int cb = chunk * 16;
            float4 c00 = *(const float4*)(memTb + b00 + cb);
            float4 c01 = *(const float4*)(memTb + b01 + cb);
            float4 c10 = *(const float4*)(memTb + b10 + cb);
            float4 c11 = *(const float4*)(memTb + b11 + cb);
            float s0 = w00*c00.x + w01*c01.x + w10*c10.x + w11*c11.x;
            float s1 = w00*c00.y + w01*c01.y + w10*c10.y + w11*c11.y;
            float s2 = w00*c00.z + w01*c01.z + w10*c10.z + w11*c11.z;
            float s3 = w00*c00.w + w01*c01.w + w10*c10.w + w11*c11.w;
            uint16_t h0,h1,h2,h3,l0,l1,l2,l3;
            bf16split(s0, h0, l0);
            bf16split(s1, h1, l1);
            bf16split(s2, h2, l2);
            bf16split(s3, h3, l3);
            u64 hiq = ((u64)h3 << 48) | ((u64)h2 << 32) | ((u64)h1 << 16) | h0;
            u64 loq = ((u64)l3 << 48) | ((u64)l2 << 32) | ((u64)l1 << 16) | l0;
            const int px = wbase + sub;
            const uint32_t off = SWB(px, chunk*8);
            *(u64*)(Ahi + off) = hiq;
            *(u64*)(Alo + off) = loq;
        }

        __syncthreads();   // B visible everywhere; own A done (warp-private)

        // ---- MMA: 4 k-steps x 8 n-tiles x 3 split terms ----
        {
            const int arow = wbase + (lane & 15);
            const int acolh = ((lane >> 4) & 1) * 16;
            const int brow_base = lane & 7;
            const int bcolh = ((lane >> 3) & 1) * 16;
            #pragma unroll
            for (int ks = 0; ks < 4; ks++) {
                uint32_t Afh[4], Afl[4];
                uint32_t aoff = SWB(arow, ks*32 + acolh);
                ldsm_x4(Afh, ahi_u + aoff);
                ldsm_x4(Afl, alo_u + aoff);
                #pragma unroll
                for (int nt = 0; nt < 8; nt++) {
                    const int brow = nt*8 + brow_base;
                    uint32_t boff = SWB(brow, ks*32 + bcolh);
                    uint32_t Bfh[2], Bfl[2];
                    ldsm_x2(Bfh, bhi_u + boff);
                    ldsm_x2(Bfl, blo_u + boff);
                    mma16816(C[nt], Afh, Bfh);
                    mma16816(C[nt], Afl, Bfh);
                    mma16816(C[nt], Afh, Bfl);
                }
            }
        }
    }

    // ---- epilogue: C fragment -> out[b][o][h][w] ----
    {
        const int g = lane >> 2, t = lane & 3;
        const int m0 = wbase + g;
        float* ob = out + (size_t)b*CO_*HW_ + h*W_;
        #pragma unroll
        for (int nt = 0; nt < 8; nt++) {
            const int n0 = nt*8 + 2*t;
            ob[(size_t)n0*HW_ + m0]         = C[nt][0];
            ob[(size_t)(n0+1)*HW_ + m0]     = C[nt][1];
            ob[(size_t)n0*HW_ + m0 + 8]     = C[nt][2];
            ob[(size_t)(n0+1)*HW_ + m0 + 8] = C[nt][3];
        }
    }
}

extern "C" void kernel_launch(void* const* d_in, const int* in_sizes, int n_in,
                              void* d_out, int out_size) {
    const float* mem   = (const float*)d_in[0];
    const float* que   = (const float*)d_in[1];
    const float* w_off = (const float*)d_in[2];
    const float* b_off = (const float*)d_in[3];
    const float* w_def = (const float*)d_in[4];
    float* out = (float*)d_out;

    prep_weights_kernel<<<(N_WB + N_WO + 255)/256, 256>>>(w_off, w_def);
    transpose_x_kernel<<<B_*H_, 256>>>(mem, que);
    offset_mma_kernel<<<B_*H_, 256>>>(b_off);
    deform_mma_kernel<<<B_*H_, 256>>>(out);
}